// round 1
// baseline (speedup 1.0000x reference)
#include <cuda_runtime.h>
#include <cuda_bf16.h>
#include <math.h>

// ---------------- problem constants ----------------
#define IN_DIM 256
#define HID 64
#define OUTD 16
#define NEG_SLOPE 0.01f

#define MAXN 50048
#define MAXE 1600000

// ---------------- device scratch (static, no allocs) ----------------
__device__ float g_Hw0[(size_t)MAXN * HID];   // X @ W0
__device__ float g_H  [(size_t)MAXN * HID];   // layer-0 output (post ELU)
__device__ float g_Hw1[(size_t)MAXN * OUTD];  // H @ W1
__device__ float g_pr0[MAXN], g_pc0[MAXN];
__device__ float g_pr1[MAXN], g_pc1[MAXN];
__device__ int   g_cnt[MAXN];
__device__ int   g_rowptr[MAXN + 1];
__device__ int   g_off[MAXN];
__device__ int   g_col[MAXE];

// ---------------- CSR build ----------------
__global__ void zero_cnt_kernel(int n) {
    int i = blockIdx.x * blockDim.x + threadIdx.x;
    if (i < n) g_cnt[i] = 0;
}

__global__ void count_kernel(const int* __restrict__ ei, int E) {
    int e = blockIdx.x * blockDim.x + threadIdx.x;
    if (e < E) atomicAdd(&g_cnt[ei[e]], 1);
}

// single-block exclusive scan over g_cnt -> g_rowptr, g_off
__global__ void scan_kernel(int n) {
    __shared__ int wsum[32];
    __shared__ int s_carry;
    int tid = threadIdx.x, lane = tid & 31, wid = tid >> 5;
    if (tid == 0) s_carry = 0;
    __syncthreads();
    for (int base = 0; base < n; base += 1024) {
        int i = base + tid;
        int v = (i < n) ? g_cnt[i] : 0;
        int x = v;
        #pragma unroll
        for (int o = 1; o < 32; o <<= 1) {
            int y = __shfl_up_sync(0xffffffffu, x, o);
            if (lane >= o) x += y;
        }
        if (lane == 31) wsum[wid] = x;
        __syncthreads();
        if (wid == 0) {
            int w = wsum[lane];
            #pragma unroll
            for (int o = 1; o < 32; o <<= 1) {
                int y = __shfl_up_sync(0xffffffffu, w, o);
                if (lane >= o) w += y;
            }
            wsum[lane] = w;
        }
        __syncthreads();
        int incl = x + (wid > 0 ? wsum[wid - 1] : 0) + s_carry;
        if (i < n) { g_rowptr[i] = incl - v; g_off[i] = incl - v; }
        __syncthreads();
        if (tid == 1023) s_carry = incl;
        __syncthreads();
    }
    if (tid == 0) g_rowptr[n] = s_carry;
}

__global__ void scatter_kernel(const int* __restrict__ ei, int E) {
    int e = blockIdx.x * blockDim.x + threadIdx.x;
    if (e < E) {
        int r = ei[e];
        int pos = atomicAdd(&g_off[r], 1);
        g_col[pos] = ei[E + e];
    }
}

// ---------------- GEMM0: X[M,256] @ W0[256,64] -> g_Hw0 ----------------
#define BM 128
#define BN 64
#define BK 16
__global__ __launch_bounds__(256) void gemm0_kernel(
    const float* __restrict__ X, const float* __restrict__ W, int M)
{
    __shared__ float As[BK][BM];
    __shared__ float Bs[BK][BN];
    int tid = threadIdx.x;
    int block_m = blockIdx.x * BM;
    int tx = tid & 15;   // over N (4 cols each)
    int ty = tid >> 4;   // over M (8 rows each)
    float acc[8][4] = {};
    for (int k0 = 0; k0 < IN_DIM; k0 += BK) {
        #pragma unroll
        for (int i = 0; i < 2; i++) {
            int l = tid * 2 + i;       // 0..511
            int m = l >> 2;            // 0..127
            int kq = (l & 3) * 4;      // 0,4,8,12
            int gm = block_m + m;
            float4 v = (gm < M) ? *(const float4*)(X + (size_t)gm * IN_DIM + k0 + kq)
                                : make_float4(0.f, 0.f, 0.f, 0.f);
            As[kq + 0][m] = v.x; As[kq + 1][m] = v.y;
            As[kq + 2][m] = v.z; As[kq + 3][m] = v.w;
        }
        {
            int kk = tid >> 4;         // 0..15
            int nq = (tid & 15) * 4;   // 0..60
            float4 v = *(const float4*)(W + (size_t)(k0 + kk) * BN + nq);
            *(float4*)&Bs[kk][nq] = v;
        }
        __syncthreads();
        #pragma unroll
        for (int kk = 0; kk < BK; kk++) {
            float a[8], b[4];
            #pragma unroll
            for (int i = 0; i < 8; i++) a[i] = As[kk][ty * 8 + i];
            #pragma unroll
            for (int j = 0; j < 4; j++) b[j] = Bs[kk][tx * 4 + j];
            #pragma unroll
            for (int i = 0; i < 8; i++)
                #pragma unroll
                for (int j = 0; j < 4; j++) acc[i][j] += a[i] * b[j];
        }
        __syncthreads();
    }
    #pragma unroll
    for (int i = 0; i < 8; i++) {
        int gm = block_m + ty * 8 + i;
        if (gm < M) {
            float4 v = make_float4(acc[i][0], acc[i][1], acc[i][2], acc[i][3]);
            *(float4*)(g_Hw0 + (size_t)gm * HID + tx * 4) = v;
        }
    }
}

// ---------------- pr0/pc0: Hw0 @ a0 halves, warp per row ----------------
__global__ void prpc0_kernel(const float* __restrict__ a, int n) {
    int w = (blockIdx.x * blockDim.x + threadIdx.x) >> 5;
    int lane = threadIdx.x & 31;
    if (w >= n) return;
    float v0 = g_Hw0[(size_t)w * HID + lane];
    float v1 = g_Hw0[(size_t)w * HID + 32 + lane];
    float pr = v0 * a[lane] + v1 * a[32 + lane];
    float pc = v0 * a[HID + lane] + v1 * a[HID + 32 + lane];
    #pragma unroll
    for (int o = 16; o; o >>= 1) {
        pr += __shfl_xor_sync(0xffffffffu, pr, o);
        pc += __shfl_xor_sync(0xffffffffu, pc, o);
    }
    if (lane == 0) { g_pr0[w] = pr; g_pc0[w] = pc; }
}

// ---------------- layer-0 fused softmax+aggregate (D=64), warp per row ----------------
__global__ __launch_bounds__(256) void agg64_kernel(int n) {
    int w = (blockIdx.x * blockDim.x + threadIdx.x) >> 5;
    int lane = threadIdx.x & 31;
    if (w >= n) return;
    int s = g_rowptr[w], eend = g_rowptr[w + 1];
    float prr = g_pr0[w];
    float acc0 = 0.f, acc1 = 0.f, denom = 0.f;
    for (int base = s; base < eend; base += 32) {
        int j = base + lane;
        float ev = 0.f; int c = 0;
        if (j < eend) {
            c = g_col[j];
            float sc = prr + g_pc0[c];
            sc = (sc >= 0.f) ? sc : NEG_SLOPE * sc;
            ev = __expf(sc);
            denom += ev;
        }
        int cnt = min(32, eend - base);
        if (cnt == 32) {
            #pragma unroll 8
            for (int t = 0; t < 32; t++) {
                float ee = __shfl_sync(0xffffffffu, ev, t);
                int   cc = __shfl_sync(0xffffffffu, c, t);
                const float* hr = g_Hw0 + (size_t)cc * HID;
                acc0 += ee * hr[lane];
                acc1 += ee * hr[lane + 32];
            }
        } else {
            for (int t = 0; t < cnt; t++) {
                float ee = __shfl_sync(0xffffffffu, ev, t);
                int   cc = __shfl_sync(0xffffffffu, c, t);
                const float* hr = g_Hw0 + (size_t)cc * HID;
                acc0 += ee * hr[lane];
                acc1 += ee * hr[lane + 32];
            }
        }
    }
    #pragma unroll
    for (int o = 16; o; o >>= 1) denom += __shfl_xor_sync(0xffffffffu, denom, o);
    float inv = (eend > s) ? 1.0f / denom : 0.0f;
    float o0 = acc0 * inv, o1 = acc1 * inv;
    o0 = (o0 > 0.f) ? o0 : expm1f(o0);   // ELU
    o1 = (o1 > 0.f) ? o1 : expm1f(o1);
    g_H[(size_t)w * HID + lane]      = o0;
    g_H[(size_t)w * HID + lane + 32] = o1;
}

// ---------------- GEMM1 + pr1/pc1 fused: H[N,64] @ W1[64,16] ----------------
__global__ __launch_bounds__(256) void gemm1_kernel(
    const float* __restrict__ W1, const float* __restrict__ a1, int n)
{
    __shared__ float Ws[HID * OUTD];
    __shared__ float a1s[2 * OUTD];
    int tid = threadIdx.x;
    for (int i = tid; i < HID * OUTD; i += 256) Ws[i] = W1[i];
    if (tid < 2 * OUTD) a1s[tid] = a1[tid];
    __syncthreads();
    int tx = tid & 15;   // output dim
    int ty = tid >> 4;   // row within block
    int r = blockIdx.x * 16 + ty;
    int rr = min(r, n - 1);
    float acc = 0.f;
    const float* hrow = g_H + (size_t)rr * HID;
    #pragma unroll
    for (int k = 0; k < HID; k++) acc += hrow[k] * Ws[k * OUTD + tx];
    float prp = acc * a1s[tx];
    float pcp = acc * a1s[OUTD + tx];
    #pragma unroll
    for (int o = 8; o; o >>= 1) {
        prp += __shfl_down_sync(0xffffffffu, prp, o, 16);
        pcp += __shfl_down_sync(0xffffffffu, pcp, o, 16);
    }
    if (r < n) {
        g_Hw1[(size_t)r * OUTD + tx] = acc;
        if (tx == 0) { g_pr1[r] = prp; g_pc1[r] = pcp; }
    }
}

// ---------------- layer-1 fused softmax+aggregate (D=16), warp per row ----------------
__global__ __launch_bounds__(256) void agg16_kernel(float* __restrict__ out, int n) {
    int w = (blockIdx.x * blockDim.x + threadIdx.x) >> 5;
    int lane = threadIdx.x & 31;
    if (w >= n) return;
    int s = g_rowptr[w], eend = g_rowptr[w + 1];
    float prr = g_pr1[w];
    int d = lane & 15;
    float acc = 0.f, denom = 0.f;
    for (int base = s; base < eend; base += 32) {
        int j = base + lane;
        float ev = 0.f; int c = 0;
        if (j < eend) {
            c = g_col[j];
            float sc = prr + g_pc1[c];
            sc = (sc >= 0.f) ? sc : NEG_SLOPE * sc;
            ev = __expf(sc);
            denom += ev;
        }
        int cnt = min(32, eend - base);
        for (int t = 0; t < cnt; t++) {
            float ee = __shfl_sync(0xffffffffu, ev, t);
            int   cc = __shfl_sync(0xffffffffu, c, t);
            acc += ee * g_Hw1[(size_t)cc * OUTD + d];
        }
    }
    #pragma unroll
    for (int o = 16; o; o >>= 1) denom += __shfl_xor_sync(0xffffffffu, denom, o);
    float inv = (eend > s) ? 1.0f / denom : 0.0f;
    if (lane < 16) out[(size_t)w * OUTD + d] = acc * inv;
}

// ---------------- log_softmax over 16 dims, thread per row ----------------
__global__ void lsm_kernel(float* __restrict__ out, int n) {
    int r = blockIdx.x * blockDim.x + threadIdx.x;
    if (r >= n) return;
    float* p = out + (size_t)r * OUTD;
    float v[OUTD];
    #pragma unroll
    for (int i = 0; i < 4; i++) {
        float4 t = *(float4*)(p + 4 * i);
        v[4*i] = t.x; v[4*i+1] = t.y; v[4*i+2] = t.z; v[4*i+3] = t.w;
    }
    float m = v[0];
    #pragma unroll
    for (int i = 1; i < OUTD; i++) m = fmaxf(m, v[i]);
    float ssum = 0.f;
    #pragma unroll
    for (int i = 0; i < OUTD; i++) ssum += __expf(v[i] - m);
    float l = m + logf(ssum);
    #pragma unroll
    for (int i = 0; i < 4; i++) {
        float4 t = make_float4(v[4*i] - l, v[4*i+1] - l, v[4*i+2] - l, v[4*i+3] - l);
        *(float4*)(p + 4 * i) = t;
    }
}

// ---------------- launch ----------------
extern "C" void kernel_launch(void* const* d_in, const int* in_sizes, int n_in,
                              void* d_out, int out_size) {
    const float* X  = (const float*)d_in[0];
    const int*   ei = (const int*)  d_in[1];
    const float* W0 = (const float*)d_in[2];
    const float* a0 = (const float*)d_in[3];
    const float* W1 = (const float*)d_in[4];
    const float* a1 = (const float*)d_in[5];
    float* out = (float*)d_out;

    int N = in_sizes[0] / IN_DIM;
    int E = in_sizes[1] / 2;

    // CSR build (shared by both layers)
    zero_cnt_kernel<<<(N + 255) / 256, 256>>>(N);
    count_kernel<<<(E + 255) / 256, 256>>>(ei, E);
    scan_kernel<<<1, 1024>>>(N);
    scatter_kernel<<<(E + 255) / 256, 256>>>(ei, E);

    // layer 0
    gemm0_kernel<<<(N + BM - 1) / BM, 256>>>(X, W0, N);
    prpc0_kernel<<<(N * 32 + 255) / 256, 256>>>(a0, N);
    agg64_kernel<<<(N + 7) / 8, 256>>>(N);

    // layer 1
    gemm1_kernel<<<(N + 15) / 16, 256>>>(W1, a1, N);
    agg16_kernel<<<(N + 7) / 8, 256>>>(out, N);

    // output log-softmax (in place on d_out)
    lsm_kernel<<<(N + 255) / 256, 256>>>(out, N);
}

// round 2
// speedup vs baseline: 1.1954x; 1.1954x over previous
#include <cuda_runtime.h>
#include <cuda_bf16.h>
#include <math.h>

// ---------------- problem constants ----------------
#define IN_DIM 256
#define HID 64
#define OUTD 16
#define NEG_SLOPE 0.01f

#define MAXN 50048
#define MAXE 1600000

// ---------------- device scratch (static, no allocs) ----------------
__device__ __align__(16) float g_Hw0[(size_t)MAXN * HID];   // X @ W0
__device__ __align__(16) float g_H  [(size_t)MAXN * HID];   // layer-0 output (post ELU)
__device__ __align__(16) float g_Hw1[(size_t)MAXN * OUTD];  // H @ W1
__device__ float g_pr0[MAXN], g_pc0[MAXN];
__device__ float g_pr1[MAXN], g_pc1[MAXN];
__device__ __align__(16) int g_cnt[MAXN];
__device__ int   g_rowptr[MAXN + 1];
__device__ int   g_off[MAXN];
__device__ int   g_col[MAXE];

// ---------------- CSR build ----------------
__global__ void zero_cnt_kernel() {
    int i = blockIdx.x * blockDim.x + threadIdx.x;
    if (i < MAXN) g_cnt[i] = 0;
}

__global__ void count_kernel(const int* __restrict__ ei, int E) {
    int e = blockIdx.x * blockDim.x + threadIdx.x;
    if (e < E) atomicAdd(&g_cnt[ei[e]], 1);
}

// single-block exclusive scan over g_cnt -> g_rowptr, g_off (int4, 4096/iter)
__global__ void scan_kernel(int n) {
    __shared__ int wsum[32];
    __shared__ int s_carry;
    int tid = threadIdx.x, lane = tid & 31, wid = tid >> 5;
    if (tid == 0) s_carry = 0;
    __syncthreads();
    const int4* cnt4 = (const int4*)g_cnt;
    int n4 = (n + 3) >> 2;
    for (int base = 0; base < n4; base += 1024) {
        int i = base + tid;
        int4 v = (i < n4) ? cnt4[i] : make_int4(0, 0, 0, 0);
        int s1 = v.x + v.y, s2 = s1 + v.z, s3 = s2 + v.w;
        int x = s3;
        #pragma unroll
        for (int o = 1; o < 32; o <<= 1) {
            int y = __shfl_up_sync(0xffffffffu, x, o);
            if (lane >= o) x += y;
        }
        if (lane == 31) wsum[wid] = x;
        __syncthreads();
        if (wid == 0) {
            int w = wsum[lane];
            #pragma unroll
            for (int o = 1; o < 32; o <<= 1) {
                int y = __shfl_up_sync(0xffffffffu, w, o);
                if (lane >= o) w += y;
            }
            wsum[lane] = w;
        }
        __syncthreads();
        int off = s_carry + (wid > 0 ? wsum[wid - 1] : 0) + (x - s3);
        if (i < n4) {
            int idx = i * 4;
            g_rowptr[idx]     = off;      g_off[idx]     = off;
            g_rowptr[idx + 1] = off + v.x; g_off[idx + 1] = off + v.x;
            g_rowptr[idx + 2] = off + s1;  g_off[idx + 2] = off + s1;
            g_rowptr[idx + 3] = off + s2;  g_off[idx + 3] = off + s2;
        }
        __syncthreads();
        if (tid == 0) s_carry += wsum[31];
        __syncthreads();
    }
    if (tid == 0) g_rowptr[n] = s_carry;
}

__global__ void scatter_kernel(const int* __restrict__ ei, int E) {
    int e = blockIdx.x * blockDim.x + threadIdx.x;
    if (e < E) {
        int r = ei[e];
        int pos = atomicAdd(&g_off[r], 1);
        g_col[pos] = ei[E + e];
    }
}

// ---------------- GEMM0: X[M,256] @ W0[256,64] -> g_Hw0, fused pr0/pc0 ----------------
#define BM 128
#define BN 64
#define BK 16
__global__ __launch_bounds__(128) void gemm0_kernel(
    const float* __restrict__ X, const float* __restrict__ W,
    const float* __restrict__ a0, int M)
{
    __shared__ float As[BK][BM + 4];
    __shared__ float Bs[BK][BN];
    int tid = threadIdx.x;
    int tx = tid & 7;    // 8 cols each over N=64
    int ty = tid >> 3;   // 8 rows each over M=128
    int block_m = blockIdx.x * BM;
    float acc[8][8] = {};
    for (int k0 = 0; k0 < IN_DIM; k0 += BK) {
        #pragma unroll
        for (int i = 0; i < 4; i++) {
            int idx = tid + 128 * i;          // 0..511
            int m = idx >> 2;                 // 0..127
            int kq = (idx & 3) * 4;           // 0,4,8,12
            int gm = block_m + m;
            float4 v = (gm < M) ? *(const float4*)(X + (size_t)gm * IN_DIM + k0 + kq)
                                : make_float4(0.f, 0.f, 0.f, 0.f);
            As[kq + 0][m] = v.x; As[kq + 1][m] = v.y;
            As[kq + 2][m] = v.z; As[kq + 3][m] = v.w;
        }
        #pragma unroll
        for (int i = 0; i < 2; i++) {
            int idx = tid + 128 * i;          // 0..255
            int kk = idx >> 4;                // 0..15
            int nq = (idx & 15) * 4;          // 0..60
            *(float4*)&Bs[kk][nq] = *(const float4*)(W + (size_t)(k0 + kk) * BN + nq);
        }
        __syncthreads();
        #pragma unroll
        for (int kk = 0; kk < BK; kk++) {
            float a[8], b[8];
            *(float4*)(a)     = *(const float4*)&As[kk][ty * 8];
            *(float4*)(a + 4) = *(const float4*)&As[kk][ty * 8 + 4];
            *(float4*)(b)     = *(const float4*)&Bs[kk][tx * 8];
            *(float4*)(b + 4) = *(const float4*)&Bs[kk][tx * 8 + 4];
            #pragma unroll
            for (int i = 0; i < 8; i++)
                #pragma unroll
                for (int j = 0; j < 8; j++) acc[i][j] += a[i] * b[j];
        }
        __syncthreads();
    }
    // epilogue: store Hw0 + fused pr0/pc0
    float av[8], aw[8];
    #pragma unroll
    for (int j = 0; j < 8; j++) {
        av[j] = __ldg(a0 + tx * 8 + j);
        aw[j] = __ldg(a0 + HID + tx * 8 + j);
    }
    #pragma unroll
    for (int i = 0; i < 8; i++) {
        int gm = block_m + ty * 8 + i;
        float pr = 0.f, pc = 0.f;
        #pragma unroll
        for (int j = 0; j < 8; j++) { pr += acc[i][j] * av[j]; pc += acc[i][j] * aw[j]; }
        #pragma unroll
        for (int o = 4; o; o >>= 1) {
            pr += __shfl_down_sync(0xffffffffu, pr, o, 8);
            pc += __shfl_down_sync(0xffffffffu, pc, o, 8);
        }
        if (gm < M) {
            float4 v0 = make_float4(acc[i][0], acc[i][1], acc[i][2], acc[i][3]);
            float4 v1 = make_float4(acc[i][4], acc[i][5], acc[i][6], acc[i][7]);
            *(float4*)(g_Hw0 + (size_t)gm * HID + tx * 8)     = v0;
            *(float4*)(g_Hw0 + (size_t)gm * HID + tx * 8 + 4) = v1;
            if (tx == 0) { g_pr0[gm] = pr; g_pc0[gm] = pc; }
        }
    }
}

// ---------------- layer-0 fused softmax+aggregate (D=64), warp per row ----------------
__global__ __launch_bounds__(256) void agg64_kernel(int n) {
    int w = (blockIdx.x * blockDim.x + threadIdx.x) >> 5;
    int lane = threadIdx.x & 31;
    if (w >= n) return;
    int s = g_rowptr[w], e = g_rowptr[w + 1];
    float prr = g_pr0[w];
    const float2* H2 = (const float2*)g_Hw0;
    float ax = 0.f, ay = 0.f, denom = 0.f;
    for (int base = s; base < e; base += 32) {
        int j = base + lane;
        float ev = 0.f; int c = 0;
        if (j < e) {
            c = g_col[j];
            float sc = prr + g_pc0[c];
            sc = (sc >= 0.f) ? sc : NEG_SLOPE * sc;
            ev = __expf(sc);
            denom += ev;
        }
        int cnt = min(32, e - base);
        if (cnt == 32) {
            #pragma unroll 8
            for (int t = 0; t < 32; t++) {
                float ee = __shfl_sync(0xffffffffu, ev, t);
                int   cc = __shfl_sync(0xffffffffu, c, t);
                float2 h = H2[(size_t)cc * 32 + lane];
                ax += ee * h.x; ay += ee * h.y;
            }
        } else {
            for (int t = 0; t < cnt; t++) {
                float ee = __shfl_sync(0xffffffffu, ev, t);
                int   cc = __shfl_sync(0xffffffffu, c, t);
                float2 h = H2[(size_t)cc * 32 + lane];
                ax += ee * h.x; ay += ee * h.y;
            }
        }
    }
    #pragma unroll
    for (int o = 16; o; o >>= 1) denom += __shfl_xor_sync(0xffffffffu, denom, o);
    float inv = (e > s) ? 1.0f / denom : 0.0f;
    float ox = ax * inv, oy = ay * inv;
    ox = (ox > 0.f) ? ox : expm1f(ox);   // ELU
    oy = (oy > 0.f) ? oy : expm1f(oy);
    ((float2*)g_H)[(size_t)w * 32 + lane] = make_float2(ox, oy);
}

// ---------------- GEMM1 + pr1/pc1 fused: H[N,64] @ W1[64,16] ----------------
__global__ __launch_bounds__(256) void gemm1_kernel(
    const float* __restrict__ W1, const float* __restrict__ a1, int n)
{
    __shared__ float Ws[HID * OUTD];     // 4KB
    __shared__ float a1s[2 * OUTD];
    __shared__ float Hs[16][HID + 4];
    int tid = threadIdx.x;
    ((float4*)Ws)[tid] = ((const float4*)W1)[tid];   // 256 float4 = 1024 floats exactly
    if (tid < 2 * OUTD) a1s[tid] = a1[tid];
    int r0 = blockIdx.x * 16;
    {
        int row = tid >> 4;
        int off = (tid & 15) * 4;
        int gr = r0 + row;
        float4 v = (gr < n) ? *(const float4*)(g_H + (size_t)gr * HID + off)
                            : make_float4(0.f, 0.f, 0.f, 0.f);
        *(float4*)&Hs[row][off] = v;
    }
    __syncthreads();
    int tx = tid & 15;   // output dim
    int ty = tid >> 4;   // row within block
    float acc = 0.f;
    #pragma unroll
    for (int k = 0; k < HID; k++) acc += Hs[ty][k] * Ws[k * OUTD + tx];
    float prp = acc * a1s[tx];
    float pcp = acc * a1s[OUTD + tx];
    #pragma unroll
    for (int o = 8; o; o >>= 1) {
        prp += __shfl_down_sync(0xffffffffu, prp, o, 16);
        pcp += __shfl_down_sync(0xffffffffu, pcp, o, 16);
    }
    int r = r0 + ty;
    if (r < n) {
        g_Hw1[(size_t)r * OUTD + tx] = acc;
        if (tx == 0) { g_pr1[r] = prp; g_pc1[r] = pcp; }
    }
}

// ---------------- layer-1 fused softmax+aggregate (D=16) + log_softmax ----------------
__global__ __launch_bounds__(256) void agg16_kernel(float* __restrict__ out, int n) {
    int w = (blockIdx.x * blockDim.x + threadIdx.x) >> 5;
    int lane = threadIdx.x & 31;
    if (w >= n) return;
    int s = g_rowptr[w], e = g_rowptr[w + 1];
    float prr = g_pr1[w];
    int sub = lane >> 2;     // which edge within group of 8
    int dk  = lane & 3;      // which float4 of the 16-dim row
    const float4* H4 = (const float4*)g_Hw1;
    float4 acc = make_float4(0.f, 0.f, 0.f, 0.f);
    float denom = 0.f;
    for (int base = s; base < e; base += 32) {
        int j = base + lane;
        float ev = 0.f; int c = 0;
        if (j < e) {
            c = g_col[j];
            float sc = prr + g_pc1[c];
            sc = (sc >= 0.f) ? sc : NEG_SLOPE * sc;
            ev = __expf(sc);
            denom += ev;
        }
        int cnt = min(32, e - base);
        int ng = (cnt + 7) >> 3;           // groups of 8 edges
        for (int t = 0; t < ng; t++) {
            int idx = t * 8 + sub;         // <= 31 always
            float ee = __shfl_sync(0xffffffffu, ev, idx);  // 0 for invalid edges
            int   cc = __shfl_sync(0xffffffffu, c, idx);
            float4 h = H4[(size_t)cc * 4 + dk];
            acc.x += ee * h.x; acc.y += ee * h.y;
            acc.z += ee * h.z; acc.w += ee * h.w;
        }
    }
    #pragma unroll
    for (int o = 16; o; o >>= 1) denom += __shfl_xor_sync(0xffffffffu, denom, o);
    float inv = (e > s) ? 1.0f / denom : 0.0f;
    // reduce acc across the 8 edge-subgroups (lanes differing in bits 2..4)
    #pragma unroll
    for (int o = 4; o <= 16; o <<= 1) {
        acc.x += __shfl_xor_sync(0xffffffffu, acc.x, o);
        acc.y += __shfl_xor_sync(0xffffffffu, acc.y, o);
        acc.z += __shfl_xor_sync(0xffffffffu, acc.z, o);
        acc.w += __shfl_xor_sync(0xffffffffu, acc.w, o);
    }
    float4 v = make_float4(acc.x * inv, acc.y * inv, acc.z * inv, acc.w * inv);
    // fused log_softmax across the 4 lanes (dk 0..3) holding the 16-dim row
    float m = fmaxf(fmaxf(v.x, v.y), fmaxf(v.z, v.w));
    m = fmaxf(m, __shfl_xor_sync(0xffffffffu, m, 1));
    m = fmaxf(m, __shfl_xor_sync(0xffffffffu, m, 2));
    float se = __expf(v.x - m) + __expf(v.y - m) + __expf(v.z - m) + __expf(v.w - m);
    se += __shfl_xor_sync(0xffffffffu, se, 1);
    se += __shfl_xor_sync(0xffffffffu, se, 2);
    float l = m + logf(se);
    if (lane < 4) {
        float4 o4 = make_float4(v.x - l, v.y - l, v.z - l, v.w - l);
        ((float4*)out)[(size_t)w * 4 + dk] = o4;
    }
}

// ---------------- launch ----------------
extern "C" void kernel_launch(void* const* d_in, const int* in_sizes, int n_in,
                              void* d_out, int out_size) {
    const float* X  = (const float*)d_in[0];
    const int*   ei = (const int*)  d_in[1];
    const float* W0 = (const float*)d_in[2];
    const float* a0 = (const float*)d_in[3];
    const float* W1 = (const float*)d_in[4];
    const float* a1 = (const float*)d_in[5];
    float* out = (float*)d_out;

    int N = in_sizes[0] / IN_DIM;
    int E = in_sizes[1] / 2;

    // CSR build (shared by both layers)
    zero_cnt_kernel<<<(MAXN + 255) / 256, 256>>>();
    count_kernel<<<(E + 255) / 256, 256>>>(ei, E);
    scan_kernel<<<1, 1024>>>(N);
    scatter_kernel<<<(E + 255) / 256, 256>>>(ei, E);

    // layer 0
    gemm0_kernel<<<(N + BM - 1) / BM, 128>>>(X, W0, a0, N);
    agg64_kernel<<<(N + 7) / 8, 256>>>(N);

    // layer 1
    gemm1_kernel<<<(N + 15) / 16, 256>>>(W1, a1, N);
    agg16_kernel<<<(N + 7) / 8, 256>>>(out, N);
}

// round 3
// speedup vs baseline: 1.2422x; 1.0391x over previous
#include <cuda_runtime.h>
#include <cuda_bf16.h>
#include <math.h>

// ---------------- problem constants ----------------
#define IN_DIM 256
#define HID 64
#define OUTD 16
#define NEG_SLOPE 0.01f

#define MAXN 50048
#define MAXE 1600000

// ---------------- device scratch (static, no allocs) ----------------
__device__ __align__(16) float g_Hw0[(size_t)MAXN * HID];   // X @ W0
__device__ __align__(16) float g_H  [(size_t)MAXN * HID];   // layer-0 output (post ELU)
__device__ __align__(16) float g_Hw1[(size_t)MAXN * OUTD];  // H @ W1
__device__ float g_pr0[MAXN], g_pc0[MAXN];
__device__ float g_pr1[MAXN], g_pc1[MAXN];
__device__ __align__(16) int g_cnt[MAXN];
__device__ int   g_rowptr[MAXN + 1];
__device__ int   g_off[MAXN];
__device__ int   g_col[MAXE];

// ---------------- CSR build ----------------
__global__ void zero_cnt_kernel() {
    int i = blockIdx.x * blockDim.x + threadIdx.x;
    if (i < MAXN) g_cnt[i] = 0;
}

__global__ void count_kernel(const int* __restrict__ ei, int E) {
    int t = blockIdx.x * blockDim.x + threadIdx.x;
    int e = t * 4;
    if (e + 3 < E) {
        int4 r = *(const int4*)(ei + e);
        atomicAdd(&g_cnt[r.x], 1);
        atomicAdd(&g_cnt[r.y], 1);
        atomicAdd(&g_cnt[r.z], 1);
        atomicAdd(&g_cnt[r.w], 1);
    } else {
        for (int j = e; j < E; j++) atomicAdd(&g_cnt[ei[j]], 1);
    }
}

// single-block exclusive scan over g_cnt -> g_rowptr, g_off (int4, 4096/iter)
__global__ void scan_kernel(int n) {
    __shared__ int wsum[32];
    __shared__ int s_carry;
    int tid = threadIdx.x, lane = tid & 31, wid = tid >> 5;
    if (tid == 0) s_carry = 0;
    __syncthreads();
    const int4* cnt4 = (const int4*)g_cnt;
    int n4 = (n + 3) >> 2;
    for (int base = 0; base < n4; base += 1024) {
        int i = base + tid;
        int4 v = (i < n4) ? cnt4[i] : make_int4(0, 0, 0, 0);
        int s1 = v.x + v.y, s2 = s1 + v.z, s3 = s2 + v.w;
        int x = s3;
        #pragma unroll
        for (int o = 1; o < 32; o <<= 1) {
            int y = __shfl_up_sync(0xffffffffu, x, o);
            if (lane >= o) x += y;
        }
        if (lane == 31) wsum[wid] = x;
        __syncthreads();
        if (wid == 0) {
            int w = wsum[lane];
            #pragma unroll
            for (int o = 1; o < 32; o <<= 1) {
                int y = __shfl_up_sync(0xffffffffu, w, o);
                if (lane >= o) w += y;
            }
            wsum[lane] = w;
        }
        __syncthreads();
        int off = s_carry + (wid > 0 ? wsum[wid - 1] : 0) + (x - s3);
        if (i < n4) {
            int idx = i * 4;
            g_rowptr[idx]     = off;       g_off[idx]     = off;
            g_rowptr[idx + 1] = off + v.x; g_off[idx + 1] = off + v.x;
            g_rowptr[idx + 2] = off + s1;  g_off[idx + 2] = off + s1;
            g_rowptr[idx + 3] = off + s2;  g_off[idx + 3] = off + s2;
        }
        __syncthreads();
        if (tid == 0) s_carry += wsum[31];
        __syncthreads();
    }
    if (tid == 0) g_rowptr[n] = s_carry;
}

__global__ void scatter_kernel(const int* __restrict__ ei, int E) {
    int t = blockIdx.x * blockDim.x + threadIdx.x;
    int e = t * 4;
    if (e + 3 < E) {
        int4 r = *(const int4*)(ei + e);
        int4 c = *(const int4*)(ei + E + e);
        int p0 = atomicAdd(&g_off[r.x], 1);
        int p1 = atomicAdd(&g_off[r.y], 1);
        int p2 = atomicAdd(&g_off[r.z], 1);
        int p3 = atomicAdd(&g_off[r.w], 1);
        g_col[p0] = c.x; g_col[p1] = c.y; g_col[p2] = c.z; g_col[p3] = c.w;
    } else {
        for (int j = e; j < E; j++) {
            int pos = atomicAdd(&g_off[ei[j]], 1);
            g_col[pos] = ei[E + j];
        }
    }
}

// ---------------- GEMM0 via tf32 tensor MMA (split precision) ----------------
// D = X@W0 with X,W0 fp32. tf32 HW truncation: pass full fp32 as "hi",
// lo = x - mask13(x). D = hi*hi + loA*hi + hi*loB (loA*loB ~2^-22, dropped).
__device__ __forceinline__ float f32_mask13(float x) {
    return __uint_as_float(__float_as_uint(x) & 0xFFFFE000u);
}

__device__ __forceinline__ void mma_tf32(float d[4], const float a[4], float b0, float b1) {
    asm volatile(
        "mma.sync.aligned.m16n8k8.row.col.f32.tf32.tf32.f32 "
        "{%0,%1,%2,%3}, {%4,%5,%6,%7}, {%8,%9}, {%0,%1,%2,%3};\n"
        : "+f"(d[0]), "+f"(d[1]), "+f"(d[2]), "+f"(d[3])
        : "r"(__float_as_uint(a[0])), "r"(__float_as_uint(a[1])),
          "r"(__float_as_uint(a[2])), "r"(__float_as_uint(a[3])),
          "r"(__float_as_uint(b0)), "r"(__float_as_uint(b1)));
}

#define GBM 128
__global__ __launch_bounds__(128) void gemm0_mma_kernel(
    const float* __restrict__ X, const float* __restrict__ W,
    const float* __restrict__ a0, int M)
{
    __shared__ float As[GBM][36];     // stride 36 -> conflict-free frag loads
    __shared__ float Bs[32][64];      // W chunk (full fp32; HW truncates to hi)
    __shared__ float Bl[32][64];      // W chunk lo part

    int tid = threadIdx.x;
    int lane = tid & 31, warp = tid >> 5;
    int gid = lane >> 2, tig = lane & 3;
    int block_m = blockIdx.x * GBM;

    float d[2][8][4];
    #pragma unroll
    for (int mt = 0; mt < 2; mt++)
        #pragma unroll
        for (int nt = 0; nt < 8; nt++)
            #pragma unroll
            for (int q = 0; q < 4; q++) d[mt][nt][q] = 0.f;

    for (int k0 = 0; k0 < IN_DIM; k0 += 32) {
        // stage A: 128 rows x 32 k
        #pragma unroll
        for (int i = 0; i < 8; i++) {
            int f = tid + 128 * i;            // 0..1023 float4 slots
            int row = f >> 3, q = (f & 7) * 4;
            int gm = block_m + row;
            float4 v = (gm < M) ? *(const float4*)(X + (size_t)gm * IN_DIM + k0 + q)
                                : make_float4(0.f, 0.f, 0.f, 0.f);
            *(float4*)&As[row][q] = v;
        }
        // stage B: 32 k x 64 n, full + lo
        #pragma unroll
        for (int i = 0; i < 4; i++) {
            int f = tid + 128 * i;            // 0..511 float4 slots
            int k = f >> 4, nq = (f & 15) * 4;
            float4 v = *(const float4*)(W + (size_t)(k0 + k) * HID + nq);
            float4 l;
            l.x = v.x - f32_mask13(v.x);
            l.y = v.y - f32_mask13(v.y);
            l.z = v.z - f32_mask13(v.z);
            l.w = v.w - f32_mask13(v.w);
            *(float4*)&Bs[k][nq] = v;
            *(float4*)&Bl[k][nq] = l;
        }
        __syncthreads();
        #pragma unroll
        for (int ks = 0; ks < 4; ks++) {
            float a[2][4], al[2][4];
            #pragma unroll
            for (int mt = 0; mt < 2; mt++) {
                int r = warp * 32 + mt * 16;
                a[mt][0] = As[r + gid][ks * 8 + tig];
                a[mt][1] = As[r + gid + 8][ks * 8 + tig];
                a[mt][2] = As[r + gid][ks * 8 + tig + 4];
                a[mt][3] = As[r + gid + 8][ks * 8 + tig + 4];
                #pragma unroll
                for (int q = 0; q < 4; q++) al[mt][q] = a[mt][q] - f32_mask13(a[mt][q]);
            }
            #pragma unroll
            for (int nt = 0; nt < 8; nt++) {
                float b0  = Bs[ks * 8 + tig][nt * 8 + gid];
                float b1  = Bs[ks * 8 + tig + 4][nt * 8 + gid];
                float bl0 = Bl[ks * 8 + tig][nt * 8 + gid];
                float bl1 = Bl[ks * 8 + tig + 4][nt * 8 + gid];
                #pragma unroll
                for (int mt = 0; mt < 2; mt++) {
                    mma_tf32(d[mt][nt], a[mt],  b0,  b1);   // hi*hi
                    mma_tf32(d[mt][nt], al[mt], b0,  b1);   // loA*hi
                    mma_tf32(d[mt][nt], a[mt],  bl0, bl1);  // hi*loB
                }
            }
        }
        __syncthreads();
    }

    // epilogue: store Hw0 + fused pr0/pc0
    float avv[8][2], aww[8][2];
    #pragma unroll
    for (int nt = 0; nt < 8; nt++) {
        avv[nt][0] = __ldg(a0 + nt * 8 + 2 * tig);
        avv[nt][1] = __ldg(a0 + nt * 8 + 2 * tig + 1);
        aww[nt][0] = __ldg(a0 + HID + nt * 8 + 2 * tig);
        aww[nt][1] = __ldg(a0 + HID + nt * 8 + 2 * tig + 1);
    }
    #pragma unroll
    for (int mt = 0; mt < 2; mt++) {
        int rloc = warp * 32 + mt * 16 + gid;
        int row0 = block_m + rloc;        // row for c0,c1
        int row1 = row0 + 8;              // row for c2,c3
        float prA = 0.f, pcA = 0.f, prB = 0.f, pcB = 0.f;
        #pragma unroll
        for (int nt = 0; nt < 8; nt++) {
            prA += d[mt][nt][0] * avv[nt][0] + d[mt][nt][1] * avv[nt][1];
            pcA += d[mt][nt][0] * aww[nt][0] + d[mt][nt][1] * aww[nt][1];
            prB += d[mt][nt][2] * avv[nt][0] + d[mt][nt][3] * avv[nt][1];
            pcB += d[mt][nt][2] * aww[nt][0] + d[mt][nt][3] * aww[nt][1];
            if (row0 < M)
                *(float2*)(g_Hw0 + (size_t)row0 * HID + nt * 8 + 2 * tig) =
                    make_float2(d[mt][nt][0], d[mt][nt][1]);
            if (row1 < M)
                *(float2*)(g_Hw0 + (size_t)row1 * HID + nt * 8 + 2 * tig) =
                    make_float2(d[mt][nt][2], d[mt][nt][3]);
        }
        #pragma unroll
        for (int o = 2; o; o >>= 1) {
            prA += __shfl_down_sync(0xffffffffu, prA, o, 4);
            pcA += __shfl_down_sync(0xffffffffu, pcA, o, 4);
            prB += __shfl_down_sync(0xffffffffu, prB, o, 4);
            pcB += __shfl_down_sync(0xffffffffu, pcB, o, 4);
        }
        if (tig == 0) {
            if (row0 < M) { g_pr0[row0] = prA; g_pc0[row0] = pcA; }
            if (row1 < M) { g_pr0[row1] = prB; g_pc0[row1] = pcB; }
        }
    }
}

// ---------------- layer-0 fused softmax+aggregate (D=64), warp per row ----------------
__global__ __launch_bounds__(256) void agg64_kernel(int n) {
    int w = (blockIdx.x * blockDim.x + threadIdx.x) >> 5;
    int lane = threadIdx.x & 31;
    if (w >= n) return;
    int s = g_rowptr[w], e = g_rowptr[w + 1];
    float prr = g_pr0[w];
    const float2* H2 = (const float2*)g_Hw0;
    float ax = 0.f, ay = 0.f, denom = 0.f;
    for (int base = s; base < e; base += 32) {
        int j = base + lane;
        float ev = 0.f; int c = 0;
        if (j < e) {
            c = g_col[j];
            float sc = prr + g_pc0[c];
            sc = (sc >= 0.f) ? sc : NEG_SLOPE * sc;
            ev = __expf(sc);
            denom += ev;
        }
        int cnt = min(32, e - base);
        if (cnt == 32) {
            #pragma unroll 8
            for (int t = 0; t < 32; t++) {
                float ee = __shfl_sync(0xffffffffu, ev, t);
                int   cc = __shfl_sync(0xffffffffu, c, t);
                float2 h = H2[(size_t)cc * 32 + lane];
                ax += ee * h.x; ay += ee * h.y;
            }
        } else {
            for (int t = 0; t < cnt; t++) {
                float ee = __shfl_sync(0xffffffffu, ev, t);
                int   cc = __shfl_sync(0xffffffffu, c, t);
                float2 h = H2[(size_t)cc * 32 + lane];
                ax += ee * h.x; ay += ee * h.y;
            }
        }
    }
    #pragma unroll
    for (int o = 16; o; o >>= 1) denom += __shfl_xor_sync(0xffffffffu, denom, o);
    float inv = (e > s) ? 1.0f / denom : 0.0f;
    float ox = ax * inv, oy = ay * inv;
    ox = (ox > 0.f) ? ox : expm1f(ox);   // ELU
    oy = (oy > 0.f) ? oy : expm1f(oy);
    ((float2*)g_H)[(size_t)w * 32 + lane] = make_float2(ox, oy);
}

// ---------------- GEMM1 + pr1/pc1 fused: H[N,64] @ W1[64,16] ----------------
__global__ __launch_bounds__(256) void gemm1_kernel(
    const float* __restrict__ W1, const float* __restrict__ a1, int n)
{
    __shared__ float Ws[HID * OUTD];     // 4KB
    __shared__ float a1s[2 * OUTD];
    __shared__ float Hs[16][HID + 4];
    int tid = threadIdx.x;
    ((float4*)Ws)[tid] = ((const float4*)W1)[tid];   // 256 float4 = 1024 floats
    if (tid < 2 * OUTD) a1s[tid] = a1[tid];
    int r0 = blockIdx.x * 16;
    {
        int row = tid >> 4;
        int off = (tid & 15) * 4;
        int gr = r0 + row;
        float4 v = (gr < n) ? *(const float4*)(g_H + (size_t)gr * HID + off)
                            : make_float4(0.f, 0.f, 0.f, 0.f);
        *(float4*)&Hs[row][off] = v;
    }
    __syncthreads();
    int tx = tid & 15;   // output dim
    int ty = tid >> 4;   // row within block
    float acc = 0.f;
    #pragma unroll
    for (int k = 0; k < HID; k++) acc += Hs[ty][k] * Ws[k * OUTD + tx];
    float prp = acc * a1s[tx];
    float pcp = acc * a1s[OUTD + tx];
    #pragma unroll
    for (int o = 8; o; o >>= 1) {
        prp += __shfl_down_sync(0xffffffffu, prp, o, 16);
        pcp += __shfl_down_sync(0xffffffffu, pcp, o, 16);
    }
    int r = r0 + ty;
    if (r < n) {
        g_Hw1[(size_t)r * OUTD + tx] = acc;
        if (tx == 0) { g_pr1[r] = prp; g_pc1[r] = pcp; }
    }
}

// ---------------- layer-1 fused softmax+aggregate (D=16) + log_softmax ----------------
__global__ __launch_bounds__(256) void agg16_kernel(float* __restrict__ out, int n) {
    int w = (blockIdx.x * blockDim.x + threadIdx.x) >> 5;
    int lane = threadIdx.x & 31;
    if (w >= n) return;
    int s = g_rowptr[w], e = g_rowptr[w + 1];
    float prr = g_pr1[w];
    int sub = lane >> 2;     // which edge within group of 8
    int dk  = lane & 3;      // which float4 of the 16-dim row
    const float4* H4 = (const float4*)g_Hw1;
    float4 acc = make_float4(0.f, 0.f, 0.f, 0.f);
    float denom = 0.f;
    for (int base = s; base < e; base += 32) {
        int j = base + lane;
        float ev = 0.f; int c = 0;
        if (j < e) {
            c = g_col[j];
            float sc = prr + g_pc1[c];
            sc = (sc >= 0.f) ? sc : NEG_SLOPE * sc;
            ev = __expf(sc);
            denom += ev;
        }
        int cnt = min(32, e - base);
        int ng = (cnt + 7) >> 3;           // groups of 8 edges
        for (int t = 0; t < ng; t++) {
            int idx = t * 8 + sub;
            float ee = __shfl_sync(0xffffffffu, ev, idx);  // 0 for invalid edges
            int   cc = __shfl_sync(0xffffffffu, c, idx);
            float4 h = H4[(size_t)cc * 4 + dk];
            acc.x += ee * h.x; acc.y += ee * h.y;
            acc.z += ee * h.z; acc.w += ee * h.w;
        }
    }
    #pragma unroll
    for (int o = 16; o; o >>= 1) denom += __shfl_xor_sync(0xffffffffu, denom, o);
    float inv = (e > s) ? 1.0f / denom : 0.0f;
    #pragma unroll
    for (int o = 4; o <= 16; o <<= 1) {
        acc.x += __shfl_xor_sync(0xffffffffu, acc.x, o);
        acc.y += __shfl_xor_sync(0xffffffffu, acc.y, o);
        acc.z += __shfl_xor_sync(0xffffffffu, acc.z, o);
        acc.w += __shfl_xor_sync(0xffffffffu, acc.w, o);
    }
    float4 v = make_float4(acc.x * inv, acc.y * inv, acc.z * inv, acc.w * inv);
    // fused log_softmax across the 4 lanes (dk 0..3) holding the 16-dim row
    float m = fmaxf(fmaxf(v.x, v.y), fmaxf(v.z, v.w));
    m = fmaxf(m, __shfl_xor_sync(0xffffffffu, m, 1));
    m = fmaxf(m, __shfl_xor_sync(0xffffffffu, m, 2));
    float se = __expf(v.x - m) + __expf(v.y - m) + __expf(v.z - m) + __expf(v.w - m);
    se += __shfl_xor_sync(0xffffffffu, se, 1);
    se += __shfl_xor_sync(0xffffffffu, se, 2);
    float l = m + logf(se);
    if (lane < 4) {
        float4 o4 = make_float4(v.x - l, v.y - l, v.z - l, v.w - l);
        ((float4*)out)[(size_t)w * 4 + dk] = o4;
    }
}

// ---------------- launch ----------------
extern "C" void kernel_launch(void* const* d_in, const int* in_sizes, int n_in,
                              void* d_out, int out_size) {
    const float* X  = (const float*)d_in[0];
    const int*   ei = (const int*)  d_in[1];
    const float* W0 = (const float*)d_in[2];
    const float* a0 = (const float*)d_in[3];
    const float* W1 = (const float*)d_in[4];
    const float* a1 = (const float*)d_in[5];
    float* out = (float*)d_out;

    int N = in_sizes[0] / IN_DIM;
    int E = in_sizes[1] / 2;

    // CSR build (shared by both layers)
    zero_cnt_kernel<<<(MAXN + 255) / 256, 256>>>();
    count_kernel<<<(E / 4 + 255) / 256, 256>>>(ei, E);
    scan_kernel<<<1, 1024>>>(N);
    scatter_kernel<<<(E / 4 + 255) / 256, 256>>>(ei, E);

    // layer 0
    gemm0_mma_kernel<<<(N + GBM - 1) / GBM, 128>>>(X, W0, a0, N);
    agg64_kernel<<<(N + 7) / 8, 256>>>(N);

    // layer 1
    gemm1_kernel<<<(N + 15) / 16, 256>>>(W1, a1, N);
    agg16_kernel<<<(N + 7) / 8, 256>>>(out, N);
}

// round 4
// speedup vs baseline: 1.4127x; 1.1373x over previous
#include <cuda_runtime.h>
#include <cuda_fp16.h>
#include <cuda_bf16.h>
#include <math.h>

// ---------------- problem constants ----------------
#define IN_DIM 256
#define HID 64
#define OUTD 16
#define NEG_SLOPE 0.01f

#define MAXN 50048
#define MAXE 1600000

// ---------------- device scratch (static, no allocs) ----------------
__device__ __align__(16) __half g_Hw0h[(size_t)MAXN * HID]; // X @ W0 (fp16 for gather)
__device__ __align__(16) float g_H  [(size_t)MAXN * HID];   // layer-0 output (post ELU)
__device__ __align__(16) float g_Hw1[(size_t)MAXN * OUTD];  // H @ W1
__device__ float g_pr0[MAXN], g_pc0[MAXN];
__device__ float g_pr1[MAXN], g_pc1[MAXN];
__device__ __align__(16) int g_cnt[MAXN];
__device__ int   g_rowptr[MAXN + 1];
__device__ __align__(16) int g_pos[MAXE];
__device__ int   g_col[MAXE];

// ---------------- CSR build ----------------
__global__ void zero_cnt_kernel() {
    int i = blockIdx.x * blockDim.x + threadIdx.x;
    if (i < MAXN) g_cnt[i] = 0;
}

// pass 1: per-edge position within its row + row counts (one atomic per edge)
__global__ void count_pos_kernel(const int* __restrict__ ei, int E) {
    int t = blockIdx.x * blockDim.x + threadIdx.x;
    int e = t * 4;
    if (e + 3 < E) {
        int4 r = *(const int4*)(ei + e);
        int4 p;
        p.x = atomicAdd(&g_cnt[r.x], 1);
        p.y = atomicAdd(&g_cnt[r.y], 1);
        p.z = atomicAdd(&g_cnt[r.z], 1);
        p.w = atomicAdd(&g_cnt[r.w], 1);
        *(int4*)(g_pos + e) = p;
    } else {
        for (int j = e; j < E; j++) g_pos[j] = atomicAdd(&g_cnt[ei[j]], 1);
    }
}

// single-block exclusive scan over g_cnt -> g_rowptr (int4, 4096/iter)
__global__ void scan_kernel(int n) {
    __shared__ int wsum[32];
    __shared__ int s_carry;
    int tid = threadIdx.x, lane = tid & 31, wid = tid >> 5;
    if (tid == 0) s_carry = 0;
    __syncthreads();
    const int4* cnt4 = (const int4*)g_cnt;
    int n4 = (n + 3) >> 2;
    for (int base = 0; base < n4; base += 1024) {
        int i = base + tid;
        int4 v = (i < n4) ? cnt4[i] : make_int4(0, 0, 0, 0);
        int s1 = v.x + v.y, s2 = s1 + v.z, s3 = s2 + v.w;
        int x = s3;
        #pragma unroll
        for (int o = 1; o < 32; o <<= 1) {
            int y = __shfl_up_sync(0xffffffffu, x, o);
            if (lane >= o) x += y;
        }
        if (lane == 31) wsum[wid] = x;
        __syncthreads();
        if (wid == 0) {
            int w = wsum[lane];
            #pragma unroll
            for (int o = 1; o < 32; o <<= 1) {
                int y = __shfl_up_sync(0xffffffffu, w, o);
                if (lane >= o) w += y;
            }
            wsum[lane] = w;
        }
        __syncthreads();
        int off = s_carry + (wid > 0 ? wsum[wid - 1] : 0) + (x - s3);
        if (i < n4) {
            int idx = i * 4;
            g_rowptr[idx]     = off;
            g_rowptr[idx + 1] = off + v.x;
            g_rowptr[idx + 2] = off + s1;
            g_rowptr[idx + 3] = off + s2;
        }
        __syncthreads();
        if (tid == 0) s_carry += wsum[31];
        __syncthreads();
    }
    if (tid == 0) g_rowptr[n] = s_carry;
}

// pass 3: atomic-free scatter using precomputed positions
__global__ void scatter_na_kernel(const int* __restrict__ ei, int E) {
    int t = blockIdx.x * blockDim.x + threadIdx.x;
    int e = t * 4;
    if (e + 3 < E) {
        int4 r = *(const int4*)(ei + e);
        int4 p = *(const int4*)(g_pos + e);
        int4 c = *(const int4*)(ei + E + e);
        g_col[g_rowptr[r.x] + p.x] = c.x;
        g_col[g_rowptr[r.y] + p.y] = c.y;
        g_col[g_rowptr[r.z] + p.z] = c.z;
        g_col[g_rowptr[r.w] + p.w] = c.w;
    } else {
        for (int j = e; j < E; j++)
            g_col[g_rowptr[ei[j]] + g_pos[j]] = ei[E + j];
    }
}

// ---------------- GEMM0 via tf32 tensor MMA (split precision) ----------------
__device__ __forceinline__ float f32_mask13(float x) {
    return __uint_as_float(__float_as_uint(x) & 0xFFFFE000u);
}

__device__ __forceinline__ void mma_tf32(float d[4], const float a[4], float b0, float b1) {
    asm volatile(
        "mma.sync.aligned.m16n8k8.row.col.f32.tf32.tf32.f32 "
        "{%0,%1,%2,%3}, {%4,%5,%6,%7}, {%8,%9}, {%0,%1,%2,%3};\n"
        : "+f"(d[0]), "+f"(d[1]), "+f"(d[2]), "+f"(d[3])
        : "r"(__float_as_uint(a[0])), "r"(__float_as_uint(a[1])),
          "r"(__float_as_uint(a[2])), "r"(__float_as_uint(a[3])),
          "r"(__float_as_uint(b0)), "r"(__float_as_uint(b1)));
}

#define GBM 128
__global__ __launch_bounds__(128) void gemm0_mma_kernel(
    const float* __restrict__ X, const float* __restrict__ W,
    const float* __restrict__ a0, int M)
{
    __shared__ float As[GBM][36];
    __shared__ float Bs[32][64];
    __shared__ float Bl[32][64];

    int tid = threadIdx.x;
    int lane = tid & 31, warp = tid >> 5;
    int gid = lane >> 2, tig = lane & 3;
    int block_m = blockIdx.x * GBM;

    float d[2][8][4];
    #pragma unroll
    for (int mt = 0; mt < 2; mt++)
        #pragma unroll
        for (int nt = 0; nt < 8; nt++)
            #pragma unroll
            for (int q = 0; q < 4; q++) d[mt][nt][q] = 0.f;

    for (int k0 = 0; k0 < IN_DIM; k0 += 32) {
        #pragma unroll
        for (int i = 0; i < 8; i++) {
            int f = tid + 128 * i;
            int row = f >> 3, q = (f & 7) * 4;
            int gm = block_m + row;
            float4 v = (gm < M) ? *(const float4*)(X + (size_t)gm * IN_DIM + k0 + q)
                                : make_float4(0.f, 0.f, 0.f, 0.f);
            *(float4*)&As[row][q] = v;
        }
        #pragma unroll
        for (int i = 0; i < 4; i++) {
            int f = tid + 128 * i;
            int k = f >> 4, nq = (f & 15) * 4;
            float4 v = *(const float4*)(W + (size_t)(k0 + k) * HID + nq);
            float4 l;
            l.x = v.x - f32_mask13(v.x);
            l.y = v.y - f32_mask13(v.y);
            l.z = v.z - f32_mask13(v.z);
            l.w = v.w - f32_mask13(v.w);
            *(float4*)&Bs[k][nq] = v;
            *(float4*)&Bl[k][nq] = l;
        }
        __syncthreads();
        #pragma unroll
        for (int ks = 0; ks < 4; ks++) {
            float a[2][4], al[2][4];
            #pragma unroll
            for (int mt = 0; mt < 2; mt++) {
                int r = warp * 32 + mt * 16;
                a[mt][0] = As[r + gid][ks * 8 + tig];
                a[mt][1] = As[r + gid + 8][ks * 8 + tig];
                a[mt][2] = As[r + gid][ks * 8 + tig + 4];
                a[mt][3] = As[r + gid + 8][ks * 8 + tig + 4];
                #pragma unroll
                for (int q = 0; q < 4; q++) al[mt][q] = a[mt][q] - f32_mask13(a[mt][q]);
            }
            #pragma unroll
            for (int nt = 0; nt < 8; nt++) {
                float b0  = Bs[ks * 8 + tig][nt * 8 + gid];
                float b1  = Bs[ks * 8 + tig + 4][nt * 8 + gid];
                float bl0 = Bl[ks * 8 + tig][nt * 8 + gid];
                float bl1 = Bl[ks * 8 + tig + 4][nt * 8 + gid];
                #pragma unroll
                for (int mt = 0; mt < 2; mt++) {
                    mma_tf32(d[mt][nt], a[mt],  b0,  b1);   // hi*hi
                    mma_tf32(d[mt][nt], al[mt], b0,  b1);   // loA*hi
                    mma_tf32(d[mt][nt], a[mt],  bl0, bl1);  // hi*loB
                }
            }
        }
        __syncthreads();
    }

    // epilogue: store Hw0 (fp16) + fused pr0/pc0 (fp32)
    float avv[8][2], aww[8][2];
    #pragma unroll
    for (int nt = 0; nt < 8; nt++) {
        avv[nt][0] = __ldg(a0 + nt * 8 + 2 * tig);
        avv[nt][1] = __ldg(a0 + nt * 8 + 2 * tig + 1);
        aww[nt][0] = __ldg(a0 + HID + nt * 8 + 2 * tig);
        aww[nt][1] = __ldg(a0 + HID + nt * 8 + 2 * tig + 1);
    }
    #pragma unroll
    for (int mt = 0; mt < 2; mt++) {
        int rloc = warp * 32 + mt * 16 + gid;
        int row0 = block_m + rloc;
        int row1 = row0 + 8;
        float prA = 0.f, pcA = 0.f, prB = 0.f, pcB = 0.f;
        #pragma unroll
        for (int nt = 0; nt < 8; nt++) {
            prA += d[mt][nt][0] * avv[nt][0] + d[mt][nt][1] * avv[nt][1];
            pcA += d[mt][nt][0] * aww[nt][0] + d[mt][nt][1] * aww[nt][1];
            prB += d[mt][nt][2] * avv[nt][0] + d[mt][nt][3] * avv[nt][1];
            pcB += d[mt][nt][2] * aww[nt][0] + d[mt][nt][3] * aww[nt][1];
            if (row0 < M)
                *(__half2*)(g_Hw0h + (size_t)row0 * HID + nt * 8 + 2 * tig) =
                    __floats2half2_rn(d[mt][nt][0], d[mt][nt][1]);
            if (row1 < M)
                *(__half2*)(g_Hw0h + (size_t)row1 * HID + nt * 8 + 2 * tig) =
                    __floats2half2_rn(d[mt][nt][2], d[mt][nt][3]);
        }
        #pragma unroll
        for (int o = 2; o; o >>= 1) {
            prA += __shfl_down_sync(0xffffffffu, prA, o, 4);
            pcA += __shfl_down_sync(0xffffffffu, pcA, o, 4);
            prB += __shfl_down_sync(0xffffffffu, prB, o, 4);
            pcB += __shfl_down_sync(0xffffffffu, pcB, o, 4);
        }
        if (tig == 0) {
            if (row0 < M) { g_pr0[row0] = prA; g_pc0[row0] = pcA; }
            if (row1 < M) { g_pr0[row1] = prB; g_pc0[row1] = pcB; }
        }
    }
}

// ---------------- layer-0 fused softmax+aggregate (D=64), warp per row ----------------
// 4 edges per step, 8 lanes per edge, LDG.128 of fp16 rows
__global__ __launch_bounds__(256) void agg64_kernel(int n) {
    int w = (blockIdx.x * blockDim.x + threadIdx.x) >> 5;
    int lane = threadIdx.x & 31;
    if (w >= n) return;
    int s = g_rowptr[w], e = g_rowptr[w + 1];
    float prr = g_pr0[w];
    int sub = lane >> 3;    // edge slot within group of 4
    int dk  = lane & 7;     // 16-byte chunk of the 128-byte fp16 row
    const uint4* H4 = (const uint4*)g_Hw0h;
    float acc[8] = {0.f, 0.f, 0.f, 0.f, 0.f, 0.f, 0.f, 0.f};
    float denom = 0.f;
    for (int base = s; base < e; base += 32) {
        int j = base + lane;
        float ev = 0.f; int c = 0;
        if (j < e) {
            c = g_col[j];
            float sc = prr + g_pc0[c];
            sc = (sc >= 0.f) ? sc : NEG_SLOPE * sc;
            ev = __expf(sc);
            denom += ev;
        }
        int cnt = min(32, e - base);
        int ng = (cnt + 3) >> 2;           // groups of 4 edges
        for (int t = 0; t < ng; t++) {
            int idx = t * 4 + sub;         // <= 31 always
            float ee = __shfl_sync(0xffffffffu, ev, idx);  // 0 for invalid edges
            int   cc = __shfl_sync(0xffffffffu, c, idx);
            uint4 hv = H4[(size_t)cc * 8 + dk];
            float2 f0 = __half22float2(*(__half2*)&hv.x);
            float2 f1 = __half22float2(*(__half2*)&hv.y);
            float2 f2 = __half22float2(*(__half2*)&hv.z);
            float2 f3 = __half22float2(*(__half2*)&hv.w);
            acc[0] += ee * f0.x; acc[1] += ee * f0.y;
            acc[2] += ee * f1.x; acc[3] += ee * f1.y;
            acc[4] += ee * f2.x; acc[5] += ee * f2.y;
            acc[6] += ee * f3.x; acc[7] += ee * f3.y;
        }
    }
    #pragma unroll
    for (int o = 16; o; o >>= 1) denom += __shfl_xor_sync(0xffffffffu, denom, o);
    // reduce acc across the 4 edge-subgroups (lane bits 3,4)
    #pragma unroll
    for (int o = 8; o <= 16; o <<= 1)
        #pragma unroll
        for (int i = 0; i < 8; i++)
            acc[i] += __shfl_xor_sync(0xffffffffu, acc[i], o);
    float inv = (e > s) ? 1.0f / denom : 0.0f;
    if (lane < 8) {
        float o8[8];
        #pragma unroll
        for (int i = 0; i < 8; i++) {
            float v = acc[i] * inv;
            o8[i] = (v > 0.f) ? v : expm1f(v);   // ELU
        }
        float* dst = g_H + (size_t)w * HID + dk * 8;
        *(float4*)(dst)     = make_float4(o8[0], o8[1], o8[2], o8[3]);
        *(float4*)(dst + 4) = make_float4(o8[4], o8[5], o8[6], o8[7]);
    }
}

// ---------------- GEMM1 + pr1/pc1 fused: H[N,64] @ W1[64,16] ----------------
__global__ __launch_bounds__(256) void gemm1_kernel(
    const float* __restrict__ W1, const float* __restrict__ a1, int n)
{
    __shared__ float Ws[HID * OUTD];
    __shared__ float a1s[2 * OUTD];
    __shared__ float Hs[16][HID + 4];
    int tid = threadIdx.x;
    ((float4*)Ws)[tid] = ((const float4*)W1)[tid];
    if (tid < 2 * OUTD) a1s[tid] = a1[tid];
    int r0 = blockIdx.x * 16;
    {
        int row = tid >> 4;
        int off = (tid & 15) * 4;
        int gr = r0 + row;
        float4 v = (gr < n) ? *(const float4*)(g_H + (size_t)gr * HID + off)
                            : make_float4(0.f, 0.f, 0.f, 0.f);
        *(float4*)&Hs[row][off] = v;
    }
    __syncthreads();
    int tx = tid & 15;
    int ty = tid >> 4;
    float acc = 0.f;
    #pragma unroll
    for (int k = 0; k < HID; k++) acc += Hs[ty][k] * Ws[k * OUTD + tx];
    float prp = acc * a1s[tx];
    float pcp = acc * a1s[OUTD + tx];
    #pragma unroll
    for (int o = 8; o; o >>= 1) {
        prp += __shfl_down_sync(0xffffffffu, prp, o, 16);
        pcp += __shfl_down_sync(0xffffffffu, pcp, o, 16);
    }
    int r = r0 + ty;
    if (r < n) {
        g_Hw1[(size_t)r * OUTD + tx] = acc;
        if (tx == 0) { g_pr1[r] = prp; g_pc1[r] = pcp; }
    }
}

// ---------------- layer-1 fused softmax+aggregate (D=16) + log_softmax ----------------
__global__ __launch_bounds__(256) void agg16_kernel(float* __restrict__ out, int n) {
    int w = (blockIdx.x * blockDim.x + threadIdx.x) >> 5;
    int lane = threadIdx.x & 31;
    if (w >= n) return;
    int s = g_rowptr[w], e = g_rowptr[w + 1];
    float prr = g_pr1[w];
    int sub = lane >> 2;     // edge within group of 8
    int dk  = lane & 3;      // float4 of the 16-dim row
    const float4* H4 = (const float4*)g_Hw1;
    float4 acc = make_float4(0.f, 0.f, 0.f, 0.f);
    float denom = 0.f;
    for (int base = s; base < e; base += 32) {
        int j = base + lane;
        float ev = 0.f; int c = 0;
        if (j < e) {
            c = g_col[j];
            float sc = prr + g_pc1[c];
            sc = (sc >= 0.f) ? sc : NEG_SLOPE * sc;
            ev = __expf(sc);
            denom += ev;
        }
        int cnt = min(32, e - base);
        int ng = (cnt + 7) >> 3;
        for (int t = 0; t < ng; t++) {
            int idx = t * 8 + sub;
            float ee = __shfl_sync(0xffffffffu, ev, idx);
            int   cc = __shfl_sync(0xffffffffu, c, idx);
            float4 h = H4[(size_t)cc * 4 + dk];
            acc.x += ee * h.x; acc.y += ee * h.y;
            acc.z += ee * h.z; acc.w += ee * h.w;
        }
    }
    #pragma unroll
    for (int o = 16; o; o >>= 1) denom += __shfl_xor_sync(0xffffffffu, denom, o);
    float inv = (e > s) ? 1.0f / denom : 0.0f;
    #pragma unroll
    for (int o = 4; o <= 16; o <<= 1) {
        acc.x += __shfl_xor_sync(0xffffffffu, acc.x, o);
        acc.y += __shfl_xor_sync(0xffffffffu, acc.y, o);
        acc.z += __shfl_xor_sync(0xffffffffu, acc.z, o);
        acc.w += __shfl_xor_sync(0xffffffffu, acc.w, o);
    }
    float4 v = make_float4(acc.x * inv, acc.y * inv, acc.z * inv, acc.w * inv);
    float m = fmaxf(fmaxf(v.x, v.y), fmaxf(v.z, v.w));
    m = fmaxf(m, __shfl_xor_sync(0xffffffffu, m, 1));
    m = fmaxf(m, __shfl_xor_sync(0xffffffffu, m, 2));
    float se = __expf(v.x - m) + __expf(v.y - m) + __expf(v.z - m) + __expf(v.w - m);
    se += __shfl_xor_sync(0xffffffffu, se, 1);
    se += __shfl_xor_sync(0xffffffffu, se, 2);
    float l = m + logf(se);
    if (lane < 4) {
        float4 o4 = make_float4(v.x - l, v.y - l, v.z - l, v.w - l);
        ((float4*)out)[(size_t)w * 4 + dk] = o4;
    }
}

// ---------------- launch ----------------
extern "C" void kernel_launch(void* const* d_in, const int* in_sizes, int n_in,
                              void* d_out, int out_size) {
    const float* X  = (const float*)d_in[0];
    const int*   ei = (const int*)  d_in[1];
    const float* W0 = (const float*)d_in[2];
    const float* a0 = (const float*)d_in[3];
    const float* W1 = (const float*)d_in[4];
    const float* a1 = (const float*)d_in[5];
    float* out = (float*)d_out;

    int N = in_sizes[0] / IN_DIM;
    int E = in_sizes[1] / 2;

    // CSR build (1.6M atomics total instead of 3.2M)
    zero_cnt_kernel<<<(MAXN + 255) / 256, 256>>>();
    count_pos_kernel<<<(E / 4 + 255) / 256, 256>>>(ei, E);
    scan_kernel<<<1, 1024>>>(N);
    scatter_na_kernel<<<(E / 4 + 255) / 256, 256>>>(ei, E);

    // layer 0
    gemm0_mma_kernel<<<(N + GBM - 1) / GBM, 128>>>(X, W0, a0, N);
    agg64_kernel<<<(N + 7) / 8, 256>>>(N);

    // layer 1
    gemm1_kernel<<<(N + 15) / 16, 256>>>(W1, a1, N);
    agg16_kernel<<<(N + 7) / 8, 256>>>(out, N);
}

// round 5
// speedup vs baseline: 1.4327x; 1.0141x over previous
#include <cuda_runtime.h>
#include <cuda_fp16.h>
#include <cuda_bf16.h>
#include <math.h>

// ---------------- problem constants ----------------
#define IN_DIM 256
#define HID 64
#define OUTD 16
#define NEG_SLOPE 0.01f

#define MAXN 50048
#define MAXE 1600000

// ---------------- device scratch (static, no allocs; zero-init at load) ----------------
__device__ __align__(16) __half g_Hw0h[(size_t)MAXN * HID]; // X @ W0 (fp16 for gather)
__device__ __align__(16) float g_H  [(size_t)MAXN * HID];   // layer-0 output (post ELU)
__device__ __align__(16) __half g_Hw1h[(size_t)MAXN * OUTD];// H @ W1 (fp16 for gather)
__device__ float g_pr0[MAXN], g_pc0[MAXN];
__device__ float g_pr1[MAXN], g_pc1[MAXN];
__device__ __align__(16) int g_cnt[MAXN];   // zero at load; scan re-zeroes each run
__device__ int   g_rowptr[MAXN + 1];
__device__ __align__(16) int g_pos[MAXE];
__device__ int   g_col[MAXE];

// ---------------- tf32 MMA helpers ----------------
__device__ __forceinline__ float f32_mask13(float x) {
    return __uint_as_float(__float_as_uint(x) & 0xFFFFE000u);
}
__device__ __forceinline__ void mma_tf32(float d[4], const float a[4], float b0, float b1) {
    asm volatile(
        "mma.sync.aligned.m16n8k8.row.col.f32.tf32.tf32.f32 "
        "{%0,%1,%2,%3}, {%4,%5,%6,%7}, {%8,%9}, {%0,%1,%2,%3};\n"
        : "+f"(d[0]), "+f"(d[1]), "+f"(d[2]), "+f"(d[3])
        : "r"(__float_as_uint(a[0])), "r"(__float_as_uint(a[1])),
          "r"(__float_as_uint(a[2])), "r"(__float_as_uint(a[3])),
          "r"(__float_as_uint(b0)), "r"(__float_as_uint(b1)));
}

// ---------------- FAT kernel: count_pos blocks + gemm0 blocks ----------------
// count blocks come FIRST so the CSR critical path (count->scan->scatter->agg)
// starts immediately; gemm0 blocks fill the rest of the chip concurrently.
#define GBM 128
#define EDGES_PER_BLK 1024

__global__ __launch_bounds__(128) void fat_kernel(
    const float* __restrict__ X, const float* __restrict__ W,
    const float* __restrict__ a0, const int* __restrict__ ei,
    int M, int E, int nCountBlks)
{
    __shared__ float As[GBM][36];
    __shared__ float Bs[32][64];
    __shared__ float Bl[32][64];

    int tid = threadIdx.x;

    if ((int)blockIdx.x < nCountBlks) {
        // ----- count + position pass: 1024 edges per block, 8 per thread -----
        int base = blockIdx.x * EDGES_PER_BLK;
        #pragma unroll
        for (int h = 0; h < 2; h++) {
            int e = base + h * 512 + tid * 4;
            if (e + 3 < E) {
                int4 r = *(const int4*)(ei + e);
                int4 p;
                p.x = atomicAdd(&g_cnt[r.x], 1);
                p.y = atomicAdd(&g_cnt[r.y], 1);
                p.z = atomicAdd(&g_cnt[r.z], 1);
                p.w = atomicAdd(&g_cnt[r.w], 1);
                *(int4*)(g_pos + e) = p;
            } else {
                for (int j = e; j < E; j++) g_pos[j] = atomicAdd(&g_cnt[ei[j]], 1);
            }
        }
        return;
    }

    // ----- gemm0 via tf32 split-precision MMA, fused pr0/pc0 epilogue -----
    int lane = tid & 31, warp = tid >> 5;
    int gid = lane >> 2, tig = lane & 3;
    int block_m = (blockIdx.x - nCountBlks) * GBM;

    float d[2][8][4];
    #pragma unroll
    for (int mt = 0; mt < 2; mt++)
        #pragma unroll
        for (int nt = 0; nt < 8; nt++)
            #pragma unroll
            for (int q = 0; q < 4; q++) d[mt][nt][q] = 0.f;

    for (int k0 = 0; k0 < IN_DIM; k0 += 32) {
        #pragma unroll
        for (int i = 0; i < 8; i++) {
            int f = tid + 128 * i;
            int row = f >> 3, q = (f & 7) * 4;
            int gm = block_m + row;
            float4 v = (gm < M) ? *(const float4*)(X + (size_t)gm * IN_DIM + k0 + q)
                                : make_float4(0.f, 0.f, 0.f, 0.f);
            *(float4*)&As[row][q] = v;
        }
        #pragma unroll
        for (int i = 0; i < 4; i++) {
            int f = tid + 128 * i;
            int k = f >> 4, nq = (f & 15) * 4;
            float4 v = *(const float4*)(W + (size_t)(k0 + k) * HID + nq);
            float4 l;
            l.x = v.x - f32_mask13(v.x);
            l.y = v.y - f32_mask13(v.y);
            l.z = v.z - f32_mask13(v.z);
            l.w = v.w - f32_mask13(v.w);
            *(float4*)&Bs[k][nq] = v;
            *(float4*)&Bl[k][nq] = l;
        }
        __syncthreads();
        #pragma unroll
        for (int ks = 0; ks < 4; ks++) {
            float a[2][4], al[2][4];
            #pragma unroll
            for (int mt = 0; mt < 2; mt++) {
                int r = warp * 32 + mt * 16;
                a[mt][0] = As[r + gid][ks * 8 + tig];
                a[mt][1] = As[r + gid + 8][ks * 8 + tig];
                a[mt][2] = As[r + gid][ks * 8 + tig + 4];
                a[mt][3] = As[r + gid + 8][ks * 8 + tig + 4];
                #pragma unroll
                for (int q = 0; q < 4; q++) al[mt][q] = a[mt][q] - f32_mask13(a[mt][q]);
            }
            #pragma unroll
            for (int nt = 0; nt < 8; nt++) {
                float b0  = Bs[ks * 8 + tig][nt * 8 + gid];
                float b1  = Bs[ks * 8 + tig + 4][nt * 8 + gid];
                float bl0 = Bl[ks * 8 + tig][nt * 8 + gid];
                float bl1 = Bl[ks * 8 + tig + 4][nt * 8 + gid];
                #pragma unroll
                for (int mt = 0; mt < 2; mt++) {
                    mma_tf32(d[mt][nt], a[mt],  b0,  b1);   // hi*hi
                    mma_tf32(d[mt][nt], al[mt], b0,  b1);   // loA*hi
                    mma_tf32(d[mt][nt], a[mt],  bl0, bl1);  // hi*loB
                }
            }
        }
        __syncthreads();
    }

    float avv[8][2], aww[8][2];
    #pragma unroll
    for (int nt = 0; nt < 8; nt++) {
        avv[nt][0] = __ldg(a0 + nt * 8 + 2 * tig);
        avv[nt][1] = __ldg(a0 + nt * 8 + 2 * tig + 1);
        aww[nt][0] = __ldg(a0 + HID + nt * 8 + 2 * tig);
        aww[nt][1] = __ldg(a0 + HID + nt * 8 + 2 * tig + 1);
    }
    #pragma unroll
    for (int mt = 0; mt < 2; mt++) {
        int rloc = warp * 32 + mt * 16 + gid;
        int row0 = block_m + rloc;
        int row1 = row0 + 8;
        float prA = 0.f, pcA = 0.f, prB = 0.f, pcB = 0.f;
        #pragma unroll
        for (int nt = 0; nt < 8; nt++) {
            prA += d[mt][nt][0] * avv[nt][0] + d[mt][nt][1] * avv[nt][1];
            pcA += d[mt][nt][0] * aww[nt][0] + d[mt][nt][1] * aww[nt][1];
            prB += d[mt][nt][2] * avv[nt][0] + d[mt][nt][3] * avv[nt][1];
            pcB += d[mt][nt][2] * aww[nt][0] + d[mt][nt][3] * aww[nt][1];
            if (row0 < M)
                *(__half2*)(g_Hw0h + (size_t)row0 * HID + nt * 8 + 2 * tig) =
                    __floats2half2_rn(d[mt][nt][0], d[mt][nt][1]);
            if (row1 < M)
                *(__half2*)(g_Hw0h + (size_t)row1 * HID + nt * 8 + 2 * tig) =
                    __floats2half2_rn(d[mt][nt][2], d[mt][nt][3]);
        }
        #pragma unroll
        for (int o = 2; o; o >>= 1) {
            prA += __shfl_down_sync(0xffffffffu, prA, o, 4);
            pcA += __shfl_down_sync(0xffffffffu, pcA, o, 4);
            prB += __shfl_down_sync(0xffffffffu, prB, o, 4);
            pcB += __shfl_down_sync(0xffffffffu, pcB, o, 4);
        }
        if (tig == 0) {
            if (row0 < M) { g_pr0[row0] = prA; g_pc0[row0] = pcA; }
            if (row1 < M) { g_pr0[row1] = prB; g_pc0[row1] = pcB; }
        }
    }
}

// ---------------- scan: exclusive prefix over g_cnt -> g_rowptr; re-zeroes g_cnt ----------------
__global__ void scan_kernel(int n) {
    __shared__ int wsum[32];
    __shared__ int s_carry;
    int tid = threadIdx.x, lane = tid & 31, wid = tid >> 5;
    if (tid == 0) s_carry = 0;
    __syncthreads();
    int4* cnt4 = (int4*)g_cnt;
    int n4 = (n + 3) >> 2;
    for (int base = 0; base < n4; base += 1024) {
        int i = base + tid;
        int4 v = make_int4(0, 0, 0, 0);
        if (i < n4) {
            v = cnt4[i];
            cnt4[i] = make_int4(0, 0, 0, 0);   // re-zero for next graph replay
        }
        int s1 = v.x + v.y, s2 = s1 + v.z, s3 = s2 + v.w;
        int x = s3;
        #pragma unroll
        for (int o = 1; o < 32; o <<= 1) {
            int y = __shfl_up_sync(0xffffffffu, x, o);
            if (lane >= o) x += y;
        }
        if (lane == 31) wsum[wid] = x;
        __syncthreads();
        if (wid == 0) {
            int w = wsum[lane];
            #pragma unroll
            for (int o = 1; o < 32; o <<= 1) {
                int y = __shfl_up_sync(0xffffffffu, w, o);
                if (lane >= o) w += y;
            }
            wsum[lane] = w;
        }
        __syncthreads();
        int off = s_carry + (wid > 0 ? wsum[wid - 1] : 0) + (x - s3);
        if (i < n4) {
            int idx = i * 4;
            g_rowptr[idx]     = off;
            g_rowptr[idx + 1] = off + v.x;
            g_rowptr[idx + 2] = off + s1;
            g_rowptr[idx + 3] = off + s2;
        }
        __syncthreads();
        if (tid == 0) s_carry += wsum[31];
        __syncthreads();
    }
    if (tid == 0) g_rowptr[n] = s_carry;
}

// ---------------- atomic-free scatter using precomputed positions ----------------
__global__ void scatter_na_kernel(const int* __restrict__ ei, int E) {
    int t = blockIdx.x * blockDim.x + threadIdx.x;
    int e = t * 4;
    if (e + 3 < E) {
        int4 r = *(const int4*)(ei + e);
        int4 p = *(const int4*)(g_pos + e);
        int4 c = *(const int4*)(ei + E + e);
        g_col[g_rowptr[r.x] + p.x] = c.x;
        g_col[g_rowptr[r.y] + p.y] = c.y;
        g_col[g_rowptr[r.z] + p.z] = c.z;
        g_col[g_rowptr[r.w] + p.w] = c.w;
    } else {
        for (int j = e; j < E; j++)
            g_col[g_rowptr[ei[j]] + g_pos[j]] = ei[E + j];
    }
}

// ---------------- layer-0 fused softmax+aggregate (D=64), warp per row ----------------
__global__ __launch_bounds__(256) void agg64_kernel(int n) {
    int w = (blockIdx.x * blockDim.x + threadIdx.x) >> 5;
    int lane = threadIdx.x & 31;
    if (w >= n) return;
    int s = g_rowptr[w], e = g_rowptr[w + 1];
    float prr = g_pr0[w];
    int sub = lane >> 3;    // edge slot within group of 4
    int dk  = lane & 7;     // 16-byte chunk of the 128-byte fp16 row
    const uint4* H4 = (const uint4*)g_Hw0h;
    float acc[8] = {0.f, 0.f, 0.f, 0.f, 0.f, 0.f, 0.f, 0.f};
    float denom = 0.f;
    for (int base = s; base < e; base += 32) {
        int j = base + lane;
        float ev = 0.f; int c = 0;
        if (j < e) {
            c = g_col[j];
            float sc = prr + g_pc0[c];
            sc = (sc >= 0.f) ? sc : NEG_SLOPE * sc;
            ev = __expf(sc);
            denom += ev;
        }
        int cnt = min(32, e - base);
        int ng = (cnt + 3) >> 2;
        for (int t = 0; t < ng; t++) {
            int idx = t * 4 + sub;
            float ee = __shfl_sync(0xffffffffu, ev, idx);  // 0 for invalid edges
            int   cc = __shfl_sync(0xffffffffu, c, idx);
            uint4 hv = H4[(size_t)cc * 8 + dk];
            float2 f0 = __half22float2(*(__half2*)&hv.x);
            float2 f1 = __half22float2(*(__half2*)&hv.y);
            float2 f2 = __half22float2(*(__half2*)&hv.z);
            float2 f3 = __half22float2(*(__half2*)&hv.w);
            acc[0] += ee * f0.x; acc[1] += ee * f0.y;
            acc[2] += ee * f1.x; acc[3] += ee * f1.y;
            acc[4] += ee * f2.x; acc[5] += ee * f2.y;
            acc[6] += ee * f3.x; acc[7] += ee * f3.y;
        }
    }
    #pragma unroll
    for (int o = 16; o; o >>= 1) denom += __shfl_xor_sync(0xffffffffu, denom, o);
    #pragma unroll
    for (int o = 8; o <= 16; o <<= 1)
        #pragma unroll
        for (int i = 0; i < 8; i++)
            acc[i] += __shfl_xor_sync(0xffffffffu, acc[i], o);
    float inv = (e > s) ? 1.0f / denom : 0.0f;
    if (lane < 8) {
        float o8[8];
        #pragma unroll
        for (int i = 0; i < 8; i++) {
            float v = acc[i] * inv;
            o8[i] = (v > 0.f) ? v : expm1f(v);   // ELU
        }
        float* dst = g_H + (size_t)w * HID + dk * 8;
        *(float4*)(dst)     = make_float4(o8[0], o8[1], o8[2], o8[3]);
        *(float4*)(dst + 4) = make_float4(o8[4], o8[5], o8[6], o8[7]);
    }
}

// ---------------- GEMM1 + pr1/pc1 fused: H[N,64] @ W1[64,16] -> fp16 ----------------
__global__ __launch_bounds__(256) void gemm1_kernel(
    const float* __restrict__ W1, const float* __restrict__ a1, int n)
{
    __shared__ float Ws[HID * OUTD];
    __shared__ float a1s[2 * OUTD];
    __shared__ float Hs[16][HID + 4];
    int tid = threadIdx.x;
    ((float4*)Ws)[tid] = ((const float4*)W1)[tid];
    if (tid < 2 * OUTD) a1s[tid] = a1[tid];
    int r0 = blockIdx.x * 16;
    {
        int row = tid >> 4;
        int off = (tid & 15) * 4;
        int gr = r0 + row;
        float4 v = (gr < n) ? *(const float4*)(g_H + (size_t)gr * HID + off)
                            : make_float4(0.f, 0.f, 0.f, 0.f);
        *(float4*)&Hs[row][off] = v;
    }
    __syncthreads();
    int tx = tid & 15;
    int ty = tid >> 4;
    float acc = 0.f;
    #pragma unroll
    for (int k = 0; k < HID; k++) acc += Hs[ty][k] * Ws[k * OUTD + tx];
    float prp = acc * a1s[tx];
    float pcp = acc * a1s[OUTD + tx];
    #pragma unroll
    for (int o = 8; o; o >>= 1) {
        prp += __shfl_down_sync(0xffffffffu, prp, o, 16);
        pcp += __shfl_down_sync(0xffffffffu, pcp, o, 16);
    }
    int r = r0 + ty;
    if (r < n) {
        g_Hw1h[(size_t)r * OUTD + tx] = __float2half_rn(acc);
        if (tx == 0) { g_pr1[r] = prp; g_pc1[r] = pcp; }
    }
}

// ---------------- layer-1 fused softmax+aggregate (D=16, fp16) + log_softmax ----------------
__global__ __launch_bounds__(256) void agg16_kernel(float* __restrict__ out, int n) {
    int w = (blockIdx.x * blockDim.x + threadIdx.x) >> 5;
    int lane = threadIdx.x & 31;
    if (w >= n) return;
    int s = g_rowptr[w], e = g_rowptr[w + 1];
    float prr = g_pr1[w];
    int sub = lane >> 1;     // edge within group of 16
    int dk  = lane & 1;      // which 16-byte half of the 32-byte fp16 row
    const uint4* H4 = (const uint4*)g_Hw1h;
    float acc[8] = {0.f, 0.f, 0.f, 0.f, 0.f, 0.f, 0.f, 0.f};
    float denom = 0.f;
    for (int base = s; base < e; base += 32) {
        int j = base + lane;
        float ev = 0.f; int c = 0;
        if (j < e) {
            c = g_col[j];
            float sc = prr + g_pc1[c];
            sc = (sc >= 0.f) ? sc : NEG_SLOPE * sc;
            ev = __expf(sc);
            denom += ev;
        }
        int cnt = min(32, e - base);
        int ng = (cnt + 15) >> 4;          // groups of 16 edges
        for (int t = 0; t < ng; t++) {
            int idx = t * 16 + sub;        // <= 31 always
            float ee = __shfl_sync(0xffffffffu, ev, idx);  // 0 for invalid edges
            int   cc = __shfl_sync(0xffffffffu, c, idx);
            uint4 hv = H4[(size_t)cc * 2 + dk];
            float2 f0 = __half22float2(*(__half2*)&hv.x);
            float2 f1 = __half22float2(*(__half2*)&hv.y);
            float2 f2 = __half22float2(*(__half2*)&hv.z);
            float2 f3 = __half22float2(*(__half2*)&hv.w);
            acc[0] += ee * f0.x; acc[1] += ee * f0.y;
            acc[2] += ee * f1.x; acc[3] += ee * f1.y;
            acc[4] += ee * f2.x; acc[5] += ee * f2.y;
            acc[6] += ee * f3.x; acc[7] += ee * f3.y;
        }
    }
    #pragma unroll
    for (int o = 16; o; o >>= 1) denom += __shfl_xor_sync(0xffffffffu, denom, o);
    // reduce across the 16 edge-subgroups (lane bits 1..4)
    #pragma unroll
    for (int o = 2; o <= 16; o <<= 1)
        #pragma unroll
        for (int i = 0; i < 8; i++)
            acc[i] += __shfl_xor_sync(0xffffffffu, acc[i], o);
    float inv = (e > s) ? 1.0f / denom : 0.0f;
    float v[8];
    #pragma unroll
    for (int i = 0; i < 8; i++) v[i] = acc[i] * inv;
    // fused log_softmax across the 2 lanes (dk 0,1) x 8 regs = 16 dims
    float m = v[0];
    #pragma unroll
    for (int i = 1; i < 8; i++) m = fmaxf(m, v[i]);
    m = fmaxf(m, __shfl_xor_sync(0xffffffffu, m, 1));
    float se = 0.f;
    #pragma unroll
    for (int i = 0; i < 8; i++) se += __expf(v[i] - m);
    se += __shfl_xor_sync(0xffffffffu, se, 1);
    float l = m + logf(se);
    if (lane < 2) {
        float* dst = out + (size_t)w * OUTD + dk * 8;
        *(float4*)(dst)     = make_float4(v[0] - l, v[1] - l, v[2] - l, v[3] - l);
        *(float4*)(dst + 4) = make_float4(v[4] - l, v[5] - l, v[6] - l, v[7] - l);
    }
}

// ---------------- launch ----------------
extern "C" void kernel_launch(void* const* d_in, const int* in_sizes, int n_in,
                              void* d_out, int out_size) {
    const float* X  = (const float*)d_in[0];
    const int*   ei = (const int*)  d_in[1];
    const float* W0 = (const float*)d_in[2];
    const float* a0 = (const float*)d_in[3];
    const float* W1 = (const float*)d_in[4];
    const float* a1 = (const float*)d_in[5];
    float* out = (float*)d_out;

    int N = in_sizes[0] / IN_DIM;
    int E = in_sizes[1] / 2;

    int nCountBlks = (E + EDGES_PER_BLK - 1) / EDGES_PER_BLK;
    int nGemmBlks  = (N + GBM - 1) / GBM;

    // fused: edge count/pos (blocks 0..nCountBlks) + gemm0 (rest), concurrent
    fat_kernel<<<nCountBlks + nGemmBlks, 128>>>(X, W0, a0, ei, N, E, nCountBlks);
    scan_kernel<<<1, 1024>>>(N);
    scatter_na_kernel<<<(E / 4 + 255) / 256, 256>>>(ei, E);

    // layer 0 aggregate
    agg64_kernel<<<(N + 7) / 8, 256>>>(N);

    // layer 1
    gemm1_kernel<<<(N + 15) / 16, 256>>>(W1, a1, N);
    agg16_kernel<<<(N + 7) / 8, 256>>>(out, N);
}